// round 1
// baseline (speedup 1.0000x reference)
#include <cuda_runtime.h>
#include <cuda_bf16.h>
#include <math.h>

#define N_NODES 50000
#define N_EDGES 800000
#define DIM_IN  128
#define DIM_H   64
#define DIM_OUT 16

// Scratch (allocation-free: __device__ globals)
__device__ float g_h0[N_NODES * DIM_H];   // x @ W1
__device__ float g_h1[N_NODES * DIM_H];   // spmm1 accumulator
__device__ float g_t2[N_NODES * DIM_H];   // tanh(h1) @ W2
__device__ float g_h2[N_NODES * DIM_H];   // spmm2 accumulator
__device__ float g_t3[N_NODES * DIM_OUT]; // h2 @ W3
__device__ float g_h3[N_NODES * DIM_OUT]; // spmm3 accumulator

// ---------------- zero accumulators ----------------
__global__ void zero_kernel() {
    int i = blockIdx.x * blockDim.x + threadIdx.x;
    if (i < N_NODES * DIM_H) {
        g_h1[i] = 0.0f;
        g_h2[i] = 0.0f;
    }
    if (i < N_NODES * DIM_OUT) {
        g_h3[i] = 0.0f;
    }
}

// ---------------- GEMM1: h0 = x @ W1  (50000x128 @ 128x64) ----------------
// 16 rows per block, 256 threads, W1 + x-rows staged in smem.
__global__ void gemm1_kernel(const float* __restrict__ x,
                             const float* __restrict__ W1) {
    __shared__ float sW[DIM_IN * DIM_H];   // 32 KB
    __shared__ float sx[16 * DIM_IN];      // 8 KB
    int tid = threadIdx.x;
    int row0 = blockIdx.x * 16;

    for (int i = tid; i < DIM_IN * DIM_H; i += 256) sW[i] = W1[i];
    for (int i = tid; i < 16 * DIM_IN; i += 256) {
        int r = i / DIM_IN, c = i % DIM_IN;
        sx[i] = (row0 + r < N_NODES) ? x[(row0 + r) * DIM_IN + c] : 0.0f;
    }
    __syncthreads();

    for (int i = tid; i < 16 * DIM_H; i += 256) {
        int r = i / DIM_H, c = i % DIM_H;
        float acc = 0.0f;
#pragma unroll
        for (int k = 0; k < DIM_IN; k++)
            acc += sx[r * DIM_IN + k] * sW[k * DIM_H + c];
        if (row0 + r < N_NODES) g_h0[(row0 + r) * DIM_H + c] = acc;
    }
}

// ---------------- SPMM (width 64): out[dst] += val * h[src] ----------------
// One warp per edge; each lane handles 2 features (float2 gather).
__global__ void spmm64_kernel(const int* __restrict__ src,
                              const int* __restrict__ dst,
                              const float* __restrict__ vals,
                              const float* __restrict__ h,
                              float* __restrict__ out) {
    int warp = (blockIdx.x * blockDim.x + threadIdx.x) >> 5;
    int lane = threadIdx.x & 31;
    if (warp >= N_EDGES) return;
    int s = src[warp];
    int d = dst[warp];
    float v = vals[warp];
    const float2* hp = (const float2*)(h + (size_t)s * DIM_H);
    float2 a = hp[lane];
    float* op = out + (size_t)d * DIM_H + lane * 2;
    atomicAdd(op, a.x * v);
    atomicAdd(op + 1, a.y * v);
}

// ---------------- GEMM2 (with tanh on input): t2 = tanh(h1) @ W2 ----------------
__global__ void gemm2_tanh_kernel(const float* __restrict__ W2) {
    __shared__ float sW[DIM_H * DIM_H];  // 16 KB
    __shared__ float sh[16 * DIM_H];     // 4 KB
    int tid = threadIdx.x;
    int row0 = blockIdx.x * 16;

    for (int i = tid; i < DIM_H * DIM_H; i += 256) sW[i] = W2[i];
    for (int i = tid; i < 16 * DIM_H; i += 256) {
        int r = i / DIM_H, c = i % DIM_H;
        sh[i] = (row0 + r < N_NODES) ? tanhf(g_h1[(row0 + r) * DIM_H + c]) : 0.0f;
    }
    __syncthreads();

    for (int i = tid; i < 16 * DIM_H; i += 256) {
        int r = i / DIM_H, c = i % DIM_H;
        float acc = 0.0f;
#pragma unroll
        for (int k = 0; k < DIM_H; k++)
            acc += sh[r * DIM_H + k] * sW[k * DIM_H + c];
        if (row0 + r < N_NODES) g_t2[(row0 + r) * DIM_H + c] = acc;
    }
}

// ---------------- GEMM3: t3 = h2 @ W3  (50000x64 @ 64x16) ----------------
// 32 rows per block, 256 threads -> 512 outputs, 2 per thread.
__global__ void gemm3_kernel(const float* __restrict__ W3) {
    __shared__ float sW[DIM_H * DIM_OUT];  // 4 KB
    __shared__ float sh[32 * DIM_H];       // 8 KB
    int tid = threadIdx.x;
    int row0 = blockIdx.x * 32;

    for (int i = tid; i < DIM_H * DIM_OUT; i += 256) sW[i] = W3[i];
    for (int i = tid; i < 32 * DIM_H; i += 256) {
        int r = i / DIM_H, c = i % DIM_H;
        sh[i] = (row0 + r < N_NODES) ? g_h2[(row0 + r) * DIM_H + c] : 0.0f;
    }
    __syncthreads();

    for (int i = tid; i < 32 * DIM_OUT; i += 256) {
        int r = i / DIM_OUT, c = i % DIM_OUT;
        float acc = 0.0f;
#pragma unroll
        for (int k = 0; k < DIM_H; k++)
            acc += sh[r * DIM_H + k] * sW[k * DIM_OUT + c];
        if (row0 + r < N_NODES) g_t3[(row0 + r) * DIM_OUT + c] = acc;
    }
}

// ---------------- SPMM (width 16) ----------------
// Thread per (edge, feature); 2 edges per warp.
__global__ void spmm16_kernel(const int* __restrict__ src,
                              const int* __restrict__ dst,
                              const float* __restrict__ vals) {
    long long idx = (long long)blockIdx.x * blockDim.x + threadIdx.x;
    if (idx >= (long long)N_EDGES * DIM_OUT) return;
    int e = (int)(idx >> 4);
    int f = (int)(idx & 15);
    int s = src[e];
    int d = dst[e];
    float v = vals[e];
    atomicAdd(&g_h3[(size_t)d * DIM_OUT + f], g_t3[(size_t)s * DIM_OUT + f] * v);
}

// ---------------- softmax over dim 16 ----------------
__global__ void softmax_kernel(float* __restrict__ out) {
    int r = blockIdx.x * blockDim.x + threadIdx.x;
    if (r >= N_NODES) return;
    const float4* p = (const float4*)(g_h3 + (size_t)r * DIM_OUT);
    float4 v0 = p[0], v1 = p[1], v2 = p[2], v3 = p[3];
    float vals[16] = {v0.x, v0.y, v0.z, v0.w, v1.x, v1.y, v1.z, v1.w,
                      v2.x, v2.y, v2.z, v2.w, v3.x, v3.y, v3.z, v3.w};
    float m = vals[0];
#pragma unroll
    for (int i = 1; i < 16; i++) m = fmaxf(m, vals[i]);
    float sum = 0.0f;
#pragma unroll
    for (int i = 0; i < 16; i++) {
        vals[i] = expf(vals[i] - m);
        sum += vals[i];
    }
    float inv = 1.0f / sum;
    float4* q = (float4*)(out + (size_t)r * DIM_OUT);
    q[0] = make_float4(vals[0] * inv, vals[1] * inv, vals[2] * inv, vals[3] * inv);
    q[1] = make_float4(vals[4] * inv, vals[5] * inv, vals[6] * inv, vals[7] * inv);
    q[2] = make_float4(vals[8] * inv, vals[9] * inv, vals[10] * inv, vals[11] * inv);
    q[3] = make_float4(vals[12] * inv, vals[13] * inv, vals[14] * inv, vals[15] * inv);
}

extern "C" void kernel_launch(void* const* d_in, const int* in_sizes, int n_in,
                              void* d_out, int out_size) {
    const float* x        = (const float*)d_in[0];
    const int*   edge_src = (const int*)d_in[1];
    const int*   edge_dst = (const int*)d_in[2];
    const float* edge_vals= (const float*)d_in[3];
    const float* W1       = (const float*)d_in[4];
    const float* W2       = (const float*)d_in[5];
    const float* W3       = (const float*)d_in[6];
    float* out = (float*)d_out;

    float *h0, *h1, *t2, *h2;
    cudaGetSymbolAddress((void**)&h0, g_h0);
    cudaGetSymbolAddress((void**)&h1, g_h1);
    cudaGetSymbolAddress((void**)&t2, g_t2);
    cudaGetSymbolAddress((void**)&h2, g_h2);

    // 1. zero accumulators
    zero_kernel<<<(N_NODES * DIM_H + 255) / 256, 256>>>();

    // 2. h0 = x @ W1
    gemm1_kernel<<<(N_NODES + 15) / 16, 256>>>(x, W1);

    // 3. h1 = spmm(h0)
    spmm64_kernel<<<(N_EDGES * 32 + 255) / 256, 256>>>(edge_src, edge_dst, edge_vals, h0, h1);

    // 4. t2 = tanh(h1) @ W2
    gemm2_tanh_kernel<<<(N_NODES + 15) / 16, 256>>>(W2);

    // 5. h2 = spmm(t2)
    spmm64_kernel<<<(N_EDGES * 32 + 255) / 256, 256>>>(edge_src, edge_dst, edge_vals, t2, h2);

    // 6. t3 = h2 @ W3
    gemm3_kernel<<<(N_NODES + 31) / 32, 256>>>(W3);

    // 7. h3 = spmm(t3)
    spmm16_kernel<<<((long long)N_EDGES * DIM_OUT + 255) / 256, 256>>>(edge_src, edge_dst, edge_vals);

    // 8. out = softmax(h3)
    softmax_kernel<<<(N_NODES + 255) / 256, 256>>>(out);
}

// round 2
// speedup vs baseline: 2.3909x; 2.3909x over previous
#include <cuda_runtime.h>
#include <cuda_bf16.h>
#include <math.h>

#define N_NODES 50000
#define N_EDGES 800000
#define DIM_IN  128
#define DIM_H   64
#define DIM_OUT 16

// Scratch (allocation-free: __device__ globals)
__device__ float g_h0[N_NODES * DIM_H];    // x @ W1
__device__ float g_h1[N_NODES * DIM_H];    // spmm1 accumulator (width 64)
__device__ float g_u[N_NODES * DIM_OUT];   // tanh(h1) @ (W2@W3)
__device__ float g_v[N_NODES * DIM_OUT];   // spmm2 accumulator (width 16)
__device__ float g_w[N_NODES * DIM_OUT];   // spmm3 accumulator (width 16)
__device__ float g_W23[DIM_H * DIM_OUT];   // W2 @ W3 (64x16)

__device__ __forceinline__ float tanh_fast(float x) {
    float y;
    asm("tanh.approx.f32 %0, %1;" : "=f"(y) : "f"(x));
    return y;
}

__device__ __forceinline__ void red_v4(float* p, float4 m) {
    asm volatile("red.global.add.v4.f32 [%0], {%1, %2, %3, %4};"
                 :: "l"(p), "f"(m.x), "f"(m.y), "f"(m.z), "f"(m.w)
                 : "memory");
}

// ---------------- zero accumulators ----------------
__global__ void zero_kernel() {
    int i = blockIdx.x * blockDim.x + threadIdx.x;
    if (i < N_NODES * DIM_H) g_h1[i] = 0.0f;
    if (i < N_NODES * DIM_OUT) {
        g_v[i] = 0.0f;
        g_w[i] = 0.0f;
    }
}

// ---------------- W23 = W2 @ W3  (64x64 @ 64x16) ----------------
__global__ void w23_kernel(const float* __restrict__ W2,
                           const float* __restrict__ W3) {
    int t = threadIdx.x;             // 1024 threads, one output each
    int i = t >> 4, j = t & 15;
    float acc = 0.0f;
#pragma unroll
    for (int k = 0; k < DIM_H; k++)
        acc += W2[i * DIM_H + k] * W3[k * DIM_OUT + j];
    g_W23[i * DIM_OUT + j] = acc;
}

// ---------------- GEMM1: h0 = x @ W1  (50000x128 @ 128x64) ----------------
// 16 rows/block, 256 threads, 4 consecutive output cols per thread.
__global__ void gemm1_kernel(const float* __restrict__ x,
                             const float* __restrict__ W1) {
    __shared__ float4 sW[DIM_IN * 16];   // W1 as [128][16] float4 = 32 KB
    __shared__ float  sx[16 * DIM_IN];   // 8 KB
    int tid = threadIdx.x;
    int row0 = blockIdx.x * 16;

    const float4* W4 = (const float4*)W1;
    for (int i = tid; i < DIM_IN * 16; i += 256) sW[i] = W4[i];
    for (int i = tid; i < 16 * DIM_IN; i += 256) {
        int r = i >> 7, c = i & 127;
        sx[i] = (row0 + r < N_NODES) ? x[(size_t)(row0 + r) * DIM_IN + c] : 0.0f;
    }
    __syncthreads();

    int r = tid >> 4;        // 0..15
    int c4 = tid & 15;       // float4 column 0..15
    float4 acc = make_float4(0.f, 0.f, 0.f, 0.f);
#pragma unroll
    for (int k = 0; k < DIM_IN; k++) {
        float a = sx[r * DIM_IN + k];
        float4 w = sW[k * 16 + c4];
        acc.x += a * w.x; acc.y += a * w.y;
        acc.z += a * w.z; acc.w += a * w.w;
    }
    if (row0 + r < N_NODES)
        ((float4*)(g_h0 + (size_t)(row0 + r) * DIM_H))[c4] = acc;
}

// ---------------- SPMM width 64: h1[dst] += val * h0[src] ----------------
// 16 threads per edge, one float4 chunk each, vectorized red.
__global__ void spmm64_kernel(const int* __restrict__ src,
                              const int* __restrict__ dst,
                              const float* __restrict__ vals,
                              const float* __restrict__ h,
                              float* __restrict__ out) {
    int t = blockIdx.x * blockDim.x + threadIdx.x;
    int e = t >> 4, c = t & 15;
    if (e >= N_EDGES) return;
    int s = src[e];
    int d = dst[e];
    float v = vals[e];
    float4 a = ((const float4*)(h + (size_t)s * DIM_H))[c];
    red_v4(out + (size_t)d * DIM_H + c * 4,
           make_float4(a.x * v, a.y * v, a.z * v, a.w * v));
}

// ---------------- u = tanh(h1) @ W23  (50000x64 @ 64x16) ----------------
// 32 rows/block, 512 threads, one output each.
__global__ void gemm2_tanh_kernel() {
    __shared__ float sW[DIM_H * DIM_OUT];  // 4 KB
    __shared__ float sh[32 * DIM_H];       // 8 KB
    int tid = threadIdx.x;
    int row0 = blockIdx.x * 32;

    for (int i = tid; i < DIM_H * DIM_OUT; i += 512) sW[i] = g_W23[i];
    for (int i = tid; i < 32 * DIM_H; i += 512) {
        int r = i >> 6, c = i & 63;
        sh[i] = (row0 + r < N_NODES)
                    ? tanh_fast(g_h1[(size_t)(row0 + r) * DIM_H + c]) : 0.0f;
    }
    __syncthreads();

    int r = tid >> 4;     // 0..31
    int c = tid & 15;     // 0..15
    float acc = 0.0f;
#pragma unroll
    for (int k = 0; k < DIM_H; k++)
        acc += sh[r * DIM_H + k] * sW[k * DIM_OUT + c];
    if (row0 + r < N_NODES)
        g_u[(size_t)(row0 + r) * DIM_OUT + c] = acc;
}

// ---------------- SPMM width 16: out[dst] += val * h[src] ----------------
// 4 threads per edge, one float4 chunk each.
__global__ void spmm16_kernel(const int* __restrict__ src,
                              const int* __restrict__ dst,
                              const float* __restrict__ vals,
                              const float* __restrict__ h,
                              float* __restrict__ out) {
    int t = blockIdx.x * blockDim.x + threadIdx.x;
    int e = t >> 2, c = t & 3;
    if (e >= N_EDGES) return;
    int s = src[e];
    int d = dst[e];
    float v = vals[e];
    float4 a = ((const float4*)(h + (size_t)s * DIM_OUT))[c];
    red_v4(out + (size_t)d * DIM_OUT + c * 4,
           make_float4(a.x * v, a.y * v, a.z * v, a.w * v));
}

// ---------------- softmax over dim 16 ----------------
__global__ void softmax_kernel(float* __restrict__ out) {
    int r = blockIdx.x * blockDim.x + threadIdx.x;
    if (r >= N_NODES) return;
    const float4* p = (const float4*)(g_w + (size_t)r * DIM_OUT);
    float4 v0 = p[0], v1 = p[1], v2 = p[2], v3 = p[3];
    float vals[16] = {v0.x, v0.y, v0.z, v0.w, v1.x, v1.y, v1.z, v1.w,
                      v2.x, v2.y, v2.z, v2.w, v3.x, v3.y, v3.z, v3.w};
    float m = vals[0];
#pragma unroll
    for (int i = 1; i < 16; i++) m = fmaxf(m, vals[i]);
    float sum = 0.0f;
#pragma unroll
    for (int i = 0; i < 16; i++) {
        vals[i] = __expf(vals[i] - m);
        sum += vals[i];
    }
    float inv = __frcp_rn(sum);
    float4* q = (float4*)(out + (size_t)r * DIM_OUT);
    q[0] = make_float4(vals[0] * inv, vals[1] * inv, vals[2] * inv, vals[3] * inv);
    q[1] = make_float4(vals[4] * inv, vals[5] * inv, vals[6] * inv, vals[7] * inv);
    q[2] = make_float4(vals[8] * inv, vals[9] * inv, vals[10] * inv, vals[11] * inv);
    q[3] = make_float4(vals[12] * inv, vals[13] * inv, vals[14] * inv, vals[15] * inv);
}

extern "C" void kernel_launch(void* const* d_in, const int* in_sizes, int n_in,
                              void* d_out, int out_size) {
    const float* x         = (const float*)d_in[0];
    const int*   edge_src  = (const int*)d_in[1];
    const int*   edge_dst  = (const int*)d_in[2];
    const float* edge_vals = (const float*)d_in[3];
    const float* W1        = (const float*)d_in[4];
    const float* W2        = (const float*)d_in[5];
    const float* W3        = (const float*)d_in[6];
    float* out = (float*)d_out;

    float *h0, *h1, *u, *v, *w;
    cudaGetSymbolAddress((void**)&h0, g_h0);
    cudaGetSymbolAddress((void**)&h1, g_h1);
    cudaGetSymbolAddress((void**)&u, g_u);
    cudaGetSymbolAddress((void**)&v, g_v);
    cudaGetSymbolAddress((void**)&w, g_w);

    // 1. zero accumulators + W23 = W2 @ W3 (independent, both tiny)
    zero_kernel<<<(N_NODES * DIM_H + 255) / 256, 256>>>();
    w23_kernel<<<1, 1024>>>(W2, W3);

    // 2. h0 = x @ W1
    gemm1_kernel<<<(N_NODES + 15) / 16, 256>>>(x, W1);

    // 3. h1 = spmm64(h0)
    spmm64_kernel<<<(N_EDGES * 16 + 255) / 256, 256>>>(edge_src, edge_dst, edge_vals, h0, h1);

    // 4. u = tanh(h1) @ W23
    gemm2_tanh_kernel<<<(N_NODES + 31) / 32, 512>>>();

    // 5. v = spmm16(u)
    spmm16_kernel<<<(N_EDGES * 4 + 255) / 256, 256>>>(edge_src, edge_dst, edge_vals, u, v);

    // 6. w = spmm16(v)
    spmm16_kernel<<<(N_EDGES * 4 + 255) / 256, 256>>>(edge_src, edge_dst, edge_vals, v, w);

    // 7. out = softmax(w)
    softmax_kernel<<<(N_NODES + 255) / 256, 256>>>(out);
}

// round 3
// speedup vs baseline: 2.7608x; 1.1547x over previous
#include <cuda_runtime.h>
#include <cuda_bf16.h>
#include <math.h>

#define N_NODES 50000
#define N_EDGES 800000
#define DIM_IN  128
#define DIM_H   64
#define DIM_OUT 16

// Scratch (allocation-free: __device__ globals)
__device__ float g_h0[N_NODES * DIM_H];    // x @ W1
__device__ float g_h1[N_NODES * DIM_H];    // spmm1 accumulator (width 64)
__device__ float g_u[N_NODES * DIM_OUT];   // tanh(h1) @ (W2@W3)
__device__ float g_v[N_NODES * DIM_OUT];   // spmm2 accumulator (width 16)
__device__ float g_w[N_NODES * DIM_OUT];   // spmm3 accumulator (width 16)
__device__ float g_W23[DIM_H * DIM_OUT];   // W2 @ W3 (64x16)

__device__ __forceinline__ float tanh_fast(float x) {
    float y;
    asm("tanh.approx.f32 %0, %1;" : "=f"(y) : "f"(x));
    return y;
}

__device__ __forceinline__ void red_v4(float* p, float4 m) {
    asm volatile("red.global.add.v4.f32 [%0], {%1, %2, %3, %4};"
                 :: "l"(p), "f"(m.x), "f"(m.y), "f"(m.z), "f"(m.w)
                 : "memory");
}

// ---- packed f32x2 helpers (FFMA2: PTX-only, 2x fp32 FMA throughput) ----
__device__ __forceinline__ unsigned long long pack2(float a, float b) {
    unsigned long long r;
    asm("mov.b64 %0, {%1, %2};" : "=l"(r) : "f"(a), "f"(b));
    return r;
}
__device__ __forceinline__ void fma2(unsigned long long& d,
                                     unsigned long long a,
                                     unsigned long long b) {
    asm("fma.rn.f32x2 %0, %1, %2, %0;" : "+l"(d) : "l"(a), "l"(b));
}
__device__ __forceinline__ float2 unpack2(unsigned long long v) {
    float2 f;
    asm("mov.b64 {%0, %1}, %2;" : "=f"(f.x), "=f"(f.y) : "l"(v));
    return f;
}

// ---------------- zero accumulators (float4) ----------------
__global__ void zero_kernel() {
    int i = blockIdx.x * blockDim.x + threadIdx.x;
    float4 z = make_float4(0.f, 0.f, 0.f, 0.f);
    if (i < N_NODES * DIM_H / 4) ((float4*)g_h1)[i] = z;
    if (i < N_NODES * DIM_OUT / 4) {
        ((float4*)g_v)[i] = z;
        ((float4*)g_w)[i] = z;
    }
}

// ---------------- W23 = W2 @ W3  (64x64 @ 64x16) ----------------
__global__ void w23_kernel(const float* __restrict__ W2,
                           const float* __restrict__ W3) {
    int t = threadIdx.x;             // 1024 threads, one output each
    int i = t >> 4, j = t & 15;
    float acc = 0.0f;
#pragma unroll
    for (int k = 0; k < DIM_H; k++)
        acc += W2[i * DIM_H + k] * W3[k * DIM_OUT + j];
    g_W23[i * DIM_OUT + j] = acc;
}

// ---------------- GEMM1: h0 = x @ W1  (50000x128 @ 128x64) ----------------
// 64-row tile, 256 threads, 4 rows x 4 cols per thread, f32x2 FMAs.
// Dynamic smem: sW4 (32KB) + sx4 (32KB) = 64KB.
#define G1_ROWS 64
__global__ __launch_bounds__(256) void gemm1_kernel(const float* __restrict__ x,
                                                    const float* __restrict__ W1) {
    extern __shared__ float smem[];
    float4* sW = (float4*)smem;                         // [128][16] float4
    float4* sx = (float4*)(smem + DIM_IN * DIM_H);      // [64][32] float4 (row-major x tile)
    int tid = threadIdx.x;
    int row0 = blockIdx.x * G1_ROWS;

    const float4* W4 = (const float4*)W1;
    for (int i = tid; i < DIM_IN * 16; i += 256) sW[i] = W4[i];
    const float4* x4 = (const float4*)x;  // row stride = 32 float4
    for (int i = tid; i < G1_ROWS * 32; i += 256) {
        int r = i >> 5, c = i & 31;
        sx[i] = (row0 + r < N_NODES) ? x4[(size_t)(row0 + r) * 32 + c]
                                     : make_float4(0.f, 0.f, 0.f, 0.f);
    }
    __syncthreads();

    int tx = tid & 15;       // col4 index (cols 4*tx..4*tx+3)
    int ty = tid >> 4;       // 0..15 -> rows 4*ty..4*ty+3
    unsigned long long acc[4][2];
#pragma unroll
    for (int i = 0; i < 4; i++) { acc[i][0] = 0ull; acc[i][1] = 0ull; }

    for (int k4 = 0; k4 < DIM_IN / 4; k4++) {
        // 4 k-values of W column-group tx
        float4 w0 = sW[(4 * k4 + 0) * 16 + tx];
        float4 w1 = sW[(4 * k4 + 1) * 16 + tx];
        float4 w2 = sW[(4 * k4 + 2) * 16 + tx];
        float4 w3 = sW[(4 * k4 + 3) * 16 + tx];
        unsigned long long w0a = pack2(w0.x, w0.y), w0b = pack2(w0.z, w0.w);
        unsigned long long w1a = pack2(w1.x, w1.y), w1b = pack2(w1.z, w1.w);
        unsigned long long w2a = pack2(w2.x, w2.y), w2b = pack2(w2.z, w2.w);
        unsigned long long w3a = pack2(w3.x, w3.y), w3b = pack2(w3.z, w3.w);
#pragma unroll
        for (int i = 0; i < 4; i++) {
            float4 a = sx[(4 * ty + i) * 32 + k4];   // 4 consecutive k of row
            unsigned long long a0 = pack2(a.x, a.x);
            unsigned long long a1 = pack2(a.y, a.y);
            unsigned long long a2 = pack2(a.z, a.z);
            unsigned long long a3 = pack2(a.w, a.w);
            fma2(acc[i][0], a0, w0a); fma2(acc[i][1], a0, w0b);
            fma2(acc[i][0], a1, w1a); fma2(acc[i][1], a1, w1b);
            fma2(acc[i][0], a2, w2a); fma2(acc[i][1], a2, w2b);
            fma2(acc[i][0], a3, w3a); fma2(acc[i][1], a3, w3b);
        }
    }

#pragma unroll
    for (int i = 0; i < 4; i++) {
        int row = row0 + 4 * ty + i;
        if (row < N_NODES) {
            float2 lo = unpack2(acc[i][0]), hi = unpack2(acc[i][1]);
            ((float4*)(g_h0 + (size_t)row * DIM_H))[tx] =
                make_float4(lo.x, lo.y, hi.x, hi.y);
        }
    }
}

// ---------------- SPMM width 64: h1[dst] += val * h0[src] ----------------
// 16 threads per edge, one float4 chunk each, vectorized red.
__global__ void spmm64_kernel(const int* __restrict__ src,
                              const int* __restrict__ dst,
                              const float* __restrict__ vals,
                              const float* __restrict__ h,
                              float* __restrict__ out) {
    int t = blockIdx.x * blockDim.x + threadIdx.x;
    int e = t >> 4, c = t & 15;
    if (e >= N_EDGES) return;
    int s = src[e];
    int d = dst[e];
    float v = vals[e];
    float4 a = ((const float4*)(h + (size_t)s * DIM_H))[c];
    red_v4(out + (size_t)d * DIM_H + c * 4,
           make_float4(a.x * v, a.y * v, a.z * v, a.w * v));
}

// ---------------- u = tanh(h1) @ W23  (50000x64 @ 64x16) ----------------
// 64 rows/block, 256 threads, 1 row x 4 cols per thread, padded smem.
__global__ __launch_bounds__(256) void gemm2_tanh_kernel() {
    __shared__ float sh[64 * 65];          // padded stride 65: conflict-free
    __shared__ float4 sW[DIM_H * 4];       // W23 as [64][4] float4
    int tid = threadIdx.x;
    int row0 = blockIdx.x * 64;

    const float4* W4 = (const float4*)g_W23;
    for (int i = tid; i < DIM_H * 4; i += 256) sW[i] = W4[i];
    for (int i = tid; i < 64 * 16; i += 256) {    // 64 rows x 16 float4
        int r = i >> 4, k4 = i & 15;
        float4 a = (row0 + r < N_NODES)
            ? ((const float4*)(g_h1 + (size_t)(row0 + r) * DIM_H))[k4]
            : make_float4(0.f, 0.f, 0.f, 0.f);
        float* p = sh + r * 65 + 4 * k4;
        p[0] = tanh_fast(a.x); p[1] = tanh_fast(a.y);
        p[2] = tanh_fast(a.z); p[3] = tanh_fast(a.w);
    }
    __syncthreads();

    int r = tid >> 2;      // 0..63
    int c4 = tid & 3;      // 0..3
    unsigned long long acc0 = 0ull, acc1 = 0ull;
#pragma unroll 8
    for (int k = 0; k < DIM_H; k++) {
        float a = sh[r * 65 + k];
        unsigned long long aa = pack2(a, a);
        float4 w = sW[k * 4 + c4];
        fma2(acc0, aa, pack2(w.x, w.y));
        fma2(acc1, aa, pack2(w.z, w.w));
    }
    if (row0 + r < N_NODES) {
        float2 lo = unpack2(acc0), hi = unpack2(acc1);
        ((float4*)(g_u + (size_t)(row0 + r) * DIM_OUT))[c4] =
            make_float4(lo.x, lo.y, hi.x, hi.y);
    }
}

// ---------------- SPMM width 16: out[dst] += val * h[src] ----------------
// One thread per edge: 4 independent gathers (MLP=4) + 4 red.v4.
__global__ void spmm16_kernel(const int* __restrict__ src,
                              const int* __restrict__ dst,
                              const float* __restrict__ vals,
                              const float* __restrict__ h,
                              float* __restrict__ out) {
    int e = blockIdx.x * blockDim.x + threadIdx.x;
    if (e >= N_EDGES) return;
    int s = src[e];
    int d = dst[e];
    float v = vals[e];
    const float4* hp = (const float4*)(h + (size_t)s * DIM_OUT);
    float4 a0 = hp[0], a1 = hp[1], a2 = hp[2], a3 = hp[3];
    float* op = out + (size_t)d * DIM_OUT;
    red_v4(op +  0, make_float4(a0.x * v, a0.y * v, a0.z * v, a0.w * v));
    red_v4(op +  4, make_float4(a1.x * v, a1.y * v, a1.z * v, a1.w * v));
    red_v4(op +  8, make_float4(a2.x * v, a2.y * v, a2.z * v, a2.w * v));
    red_v4(op + 12, make_float4(a3.x * v, a3.y * v, a3.z * v, a3.w * v));
}

// ---------------- softmax over dim 16 ----------------
__global__ void softmax_kernel(float* __restrict__ out) {
    int r = blockIdx.x * blockDim.x + threadIdx.x;
    if (r >= N_NODES) return;
    const float4* p = (const float4*)(g_w + (size_t)r * DIM_OUT);
    float4 v0 = p[0], v1 = p[1], v2 = p[2], v3 = p[3];
    float vals[16] = {v0.x, v0.y, v0.z, v0.w, v1.x, v1.y, v1.z, v1.w,
                      v2.x, v2.y, v2.z, v2.w, v3.x, v3.y, v3.z, v3.w};
    float m = vals[0];
#pragma unroll
    for (int i = 1; i < 16; i++) m = fmaxf(m, vals[i]);
    float sum = 0.0f;
#pragma unroll
    for (int i = 0; i < 16; i++) {
        vals[i] = __expf(vals[i] - m);
        sum += vals[i];
    }
    float inv = __frcp_rn(sum);
    float4* q = (float4*)(out + (size_t)r * DIM_OUT);
    q[0] = make_float4(vals[0] * inv, vals[1] * inv, vals[2] * inv, vals[3] * inv);
    q[1] = make_float4(vals[4] * inv, vals[5] * inv, vals[6] * inv, vals[7] * inv);
    q[2] = make_float4(vals[8] * inv, vals[9] * inv, vals[10] * inv, vals[11] * inv);
    q[3] = make_float4(vals[12] * inv, vals[13] * inv, vals[14] * inv, vals[15] * inv);
}

extern "C" void kernel_launch(void* const* d_in, const int* in_sizes, int n_in,
                              void* d_out, int out_size) {
    const float* x         = (const float*)d_in[0];
    const int*   edge_src  = (const int*)d_in[1];
    const int*   edge_dst  = (const int*)d_in[2];
    const float* edge_vals = (const float*)d_in[3];
    const float* W1        = (const float*)d_in[4];
    const float* W2        = (const float*)d_in[5];
    const float* W3        = (const float*)d_in[6];
    float* out = (float*)d_out;

    float *h0, *h1, *u, *v, *w;
    cudaGetSymbolAddress((void**)&h0, g_h0);
    cudaGetSymbolAddress((void**)&h1, g_h1);
    cudaGetSymbolAddress((void**)&u, g_u);
    cudaGetSymbolAddress((void**)&v, g_v);
    cudaGetSymbolAddress((void**)&w, g_w);

    const int G1_SMEM = (DIM_IN * DIM_H + G1_ROWS * DIM_IN) * sizeof(float); // 64KB
    cudaFuncSetAttribute(gemm1_kernel,
                         cudaFuncAttributeMaxDynamicSharedMemorySize, G1_SMEM);

    // 1. zero accumulators + W23 = W2 @ W3
    zero_kernel<<<(N_NODES * DIM_H / 4 + 255) / 256, 256>>>();
    w23_kernel<<<1, 1024>>>(W2, W3);

    // 2. h0 = x @ W1
    gemm1_kernel<<<(N_NODES + G1_ROWS - 1) / G1_ROWS, 256, G1_SMEM>>>(x, W1);

    // 3. h1 = spmm64(h0)
    spmm64_kernel<<<(N_EDGES * 16 + 255) / 256, 256>>>(edge_src, edge_dst, edge_vals, h0, h1);

    // 4. u = tanh(h1) @ W23
    gemm2_tanh_kernel<<<(N_NODES + 63) / 64, 256>>>();

    // 5. v = spmm16(u)
    spmm16_kernel<<<(N_EDGES + 255) / 256, 256>>>(edge_src, edge_dst, edge_vals, u, v);

    // 6. w = spmm16(v)
    spmm16_kernel<<<(N_EDGES + 255) / 256, 256>>>(edge_src, edge_dst, edge_vals, v, w);

    // 7. out = softmax(w)
    softmax_kernel<<<(N_NODES + 255) / 256, 256>>>(out);
}

// round 4
// speedup vs baseline: 3.3179x; 1.2018x over previous
#include <cuda_runtime.h>
#include <cuda_bf16.h>
#include <math.h>

#define N_NODES 50000
#define N_EDGES 800000
#define DIM_IN  128
#define DIM_H   64
#define DIM_OUT 16
#define SCAN_BLOCKS ((N_NODES + 1023) / 1024)   // 49

// Scratch (allocation-free: __device__ globals)
__device__ float g_h0[N_NODES * DIM_H];    // x @ W1
__device__ float g_h1[N_NODES * DIM_H];    // spmm1 result (width 64)
__device__ float g_u[N_NODES * DIM_OUT];   // tanh(h1) @ (W2@W3)
__device__ float g_v[N_NODES * DIM_OUT];   // spmm2 result (width 16)
__device__ float g_w[N_NODES * DIM_OUT];   // spmm3 result (width 16)
__device__ float g_W23[DIM_H * DIM_OUT];   // W2 @ W3 (64x16)

// CSR build scratch
__device__ int   g_hist[N_NODES];
__device__ int   g_row_ptr[N_NODES + 1];
__device__ int   g_cursor[N_NODES];
__device__ int   g_bsum[64];
__device__ int   g_srt_src[N_EDGES];
__device__ float g_srt_val[N_EDGES];

__device__ __forceinline__ float tanh_fast(float x) {
    float y;
    asm("tanh.approx.f32 %0, %1;" : "=f"(y) : "f"(x));
    return y;
}

// ---- packed f32x2 helpers ----
__device__ __forceinline__ unsigned long long pack2(float a, float b) {
    unsigned long long r;
    asm("mov.b64 %0, {%1, %2};" : "=l"(r) : "f"(a), "f"(b));
    return r;
}
__device__ __forceinline__ void fma2(unsigned long long& d,
                                     unsigned long long a,
                                     unsigned long long b) {
    asm("fma.rn.f32x2 %0, %1, %2, %0;" : "+l"(d) : "l"(a), "l"(b));
}
__device__ __forceinline__ float2 unpack2(unsigned long long v) {
    float2 f;
    asm("mov.b64 {%0, %1}, %2;" : "=f"(f.x), "=f"(f.y) : "l"(v));
    return f;
}

// ================= CSR build: counting sort by dst =================

// histogram of dst (4 edges per thread, RED adds)
__global__ void hist_kernel(const int* __restrict__ dst) {
    int t = blockIdx.x * blockDim.x + threadIdx.x;
    if (t >= N_EDGES / 4) return;
    int4 d = ((const int4*)dst)[t];
    atomicAdd(&g_hist[d.x], 1);
    atomicAdd(&g_hist[d.y], 1);
    atomicAdd(&g_hist[d.z], 1);
    atomicAdd(&g_hist[d.w], 1);
}

// per-1024-chunk exclusive scan; chunk-local result into row_ptr, totals into bsum
__global__ void scan1_kernel() {
    __shared__ int warp_sums[32];
    int tid = threadIdx.x;
    int gid = blockIdx.x * 1024 + tid;
    int lane = tid & 31, wid = tid >> 5;
    int v = (gid < N_NODES) ? g_hist[gid] : 0;
    int incl = v;
#pragma unroll
    for (int o = 1; o < 32; o <<= 1) {
        int n = __shfl_up_sync(0xffffffffu, incl, o);
        if (lane >= o) incl += n;
    }
    if (lane == 31) warp_sums[wid] = incl;
    __syncthreads();
    if (wid == 0) {
        int s = warp_sums[lane];
#pragma unroll
        for (int o = 1; o < 32; o <<= 1) {
            int n = __shfl_up_sync(0xffffffffu, s, o);
            if (lane >= o) s += n;
        }
        warp_sums[lane] = s;
    }
    __syncthreads();
    int warp_off = (wid == 0) ? 0 : warp_sums[wid - 1];
    if (gid < N_NODES) g_row_ptr[gid] = warp_off + incl - v;
    if (tid == 1023) g_bsum[blockIdx.x] = warp_off + incl;
}

// scan the 49 block sums (1 warp)
__global__ void scan2_kernel() {
    int lane = threadIdx.x;
    int total = 0;
    for (int c = 0; c < SCAN_BLOCKS; c += 32) {
        int i = c + lane;
        int v = (i < SCAN_BLOCKS) ? g_bsum[i] : 0;
        int incl = v;
#pragma unroll
        for (int o = 1; o < 32; o <<= 1) {
            int n = __shfl_up_sync(0xffffffffu, incl, o);
            if (lane >= o) incl += n;
        }
        if (i < SCAN_BLOCKS) g_bsum[i] = incl - v + total;
        total += __shfl_sync(0xffffffffu, incl, 31);
    }
    if (lane == 0) g_row_ptr[N_NODES] = total;
}

// fixup: add block offsets; init cursor
__global__ void scan3_kernel() {
    int gid = blockIdx.x * 1024 + threadIdx.x;
    if (gid < N_NODES) {
        int rp = g_row_ptr[gid] + g_bsum[blockIdx.x];
        g_row_ptr[gid] = rp;
        g_cursor[gid] = rp;
    }
}

// scatter edges into dst-sorted order (4 edges per thread)
__global__ void scatter_kernel(const int* __restrict__ src,
                               const int* __restrict__ dst,
                               const float* __restrict__ vals) {
    int t = blockIdx.x * blockDim.x + threadIdx.x;
    if (t >= N_EDGES / 4) return;
    int4 s = ((const int4*)src)[t];
    int4 d = ((const int4*)dst)[t];
    float4 v = ((const float4*)vals)[t];
    int p;
    p = atomicAdd(&g_cursor[d.x], 1); g_srt_src[p] = s.x; g_srt_val[p] = v.x;
    p = atomicAdd(&g_cursor[d.y], 1); g_srt_src[p] = s.y; g_srt_val[p] = v.y;
    p = atomicAdd(&g_cursor[d.z], 1); g_srt_src[p] = s.z; g_srt_val[p] = v.z;
    p = atomicAdd(&g_cursor[d.w], 1); g_srt_src[p] = s.w; g_srt_val[p] = v.w;
}

// ================= dense kernels =================

// W23 = W2 @ W3  (64x64 @ 64x16)
__global__ void w23_kernel(const float* __restrict__ W2,
                           const float* __restrict__ W3) {
    int t = threadIdx.x;
    int i = t >> 4, j = t & 15;
    float acc = 0.0f;
#pragma unroll
    for (int k = 0; k < DIM_H; k++)
        acc += W2[i * DIM_H + k] * W3[k * DIM_OUT + j];
    g_W23[i * DIM_OUT + j] = acc;
}

// GEMM1: h0 = x @ W1  (50000x128 @ 128x64), 64-row tile, f32x2
#define G1_ROWS 64
__global__ __launch_bounds__(256) void gemm1_kernel(const float* __restrict__ x,
                                                    const float* __restrict__ W1) {
    extern __shared__ float smem[];
    float4* sW = (float4*)smem;                       // [128][16] float4
    float4* sx = (float4*)(smem + DIM_IN * DIM_H);    // [64][32] float4
    int tid = threadIdx.x;
    int row0 = blockIdx.x * G1_ROWS;

    const float4* W4 = (const float4*)W1;
    for (int i = tid; i < DIM_IN * 16; i += 256) sW[i] = W4[i];
    const float4* x4 = (const float4*)x;
    for (int i = tid; i < G1_ROWS * 32; i += 256) {
        int r = i >> 5, c = i & 31;
        sx[i] = (row0 + r < N_NODES) ? x4[(size_t)(row0 + r) * 32 + c]
                                     : make_float4(0.f, 0.f, 0.f, 0.f);
    }
    __syncthreads();

    int tx = tid & 15;
    int ty = tid >> 4;
    unsigned long long acc[4][2];
#pragma unroll
    for (int i = 0; i < 4; i++) { acc[i][0] = 0ull; acc[i][1] = 0ull; }

    for (int k4 = 0; k4 < DIM_IN / 4; k4++) {
        float4 w0 = sW[(4 * k4 + 0) * 16 + tx];
        float4 w1 = sW[(4 * k4 + 1) * 16 + tx];
        float4 w2 = sW[(4 * k4 + 2) * 16 + tx];
        float4 w3 = sW[(4 * k4 + 3) * 16 + tx];
        unsigned long long w0a = pack2(w0.x, w0.y), w0b = pack2(w0.z, w0.w);
        unsigned long long w1a = pack2(w1.x, w1.y), w1b = pack2(w1.z, w1.w);
        unsigned long long w2a = pack2(w2.x, w2.y), w2b = pack2(w2.z, w2.w);
        unsigned long long w3a = pack2(w3.x, w3.y), w3b = pack2(w3.z, w3.w);
#pragma unroll
        for (int i = 0; i < 4; i++) {
            float4 a = sx[(4 * ty + i) * 32 + k4];
            unsigned long long a0 = pack2(a.x, a.x);
            unsigned long long a1 = pack2(a.y, a.y);
            unsigned long long a2 = pack2(a.z, a.z);
            unsigned long long a3 = pack2(a.w, a.w);
            fma2(acc[i][0], a0, w0a); fma2(acc[i][1], a0, w0b);
            fma2(acc[i][0], a1, w1a); fma2(acc[i][1], a1, w1b);
            fma2(acc[i][0], a2, w2a); fma2(acc[i][1], a2, w2b);
            fma2(acc[i][0], a3, w3a); fma2(acc[i][1], a3, w3b);
        }
    }
#pragma unroll
    for (int i = 0; i < 4; i++) {
        int row = row0 + 4 * ty + i;
        if (row < N_NODES) {
            float2 lo = unpack2(acc[i][0]), hi = unpack2(acc[i][1]);
            ((float4*)(g_h0 + (size_t)row * DIM_H))[tx] =
                make_float4(lo.x, lo.y, hi.x, hi.y);
        }
    }
}

// SPMM width 64, CSR: 16 threads per dst node, register accumulate, 1 store
__global__ __launch_bounds__(256) void spmm64_csr_kernel(const float* __restrict__ h,
                                                         float* __restrict__ out) {
    int t = blockIdx.x * blockDim.x + threadIdx.x;
    int node = t >> 4, c = t & 15;
    if (node >= N_NODES) return;
    int i = g_row_ptr[node], end = g_row_ptr[node + 1];
    float4 acc = make_float4(0.f, 0.f, 0.f, 0.f);
    for (; i + 2 <= end; i += 2) {
        int s0 = g_srt_src[i], s1 = g_srt_src[i + 1];
        float v0 = g_srt_val[i], v1 = g_srt_val[i + 1];
        float4 a0 = ((const float4*)(h + (size_t)s0 * DIM_H))[c];
        float4 a1 = ((const float4*)(h + (size_t)s1 * DIM_H))[c];
        acc.x += a0.x * v0; acc.y += a0.y * v0;
        acc.z += a0.z * v0; acc.w += a0.w * v0;
        acc.x += a1.x * v1; acc.y += a1.y * v1;
        acc.z += a1.z * v1; acc.w += a1.w * v1;
    }
    if (i < end) {
        int s0 = g_srt_src[i];
        float v0 = g_srt_val[i];
        float4 a0 = ((const float4*)(h + (size_t)s0 * DIM_H))[c];
        acc.x += a0.x * v0; acc.y += a0.y * v0;
        acc.z += a0.z * v0; acc.w += a0.w * v0;
    }
    ((float4*)(out + (size_t)node * DIM_H))[c] = acc;
}

// SPMM width 16, CSR: 4 threads per dst node
__global__ __launch_bounds__(256) void spmm16_csr_kernel(const float* __restrict__ h,
                                                         float* __restrict__ out) {
    int t = blockIdx.x * blockDim.x + threadIdx.x;
    int node = t >> 2, c = t & 3;
    if (node >= N_NODES) return;
    int i = g_row_ptr[node], end = g_row_ptr[node + 1];
    float4 acc = make_float4(0.f, 0.f, 0.f, 0.f);
    for (; i + 2 <= end; i += 2) {
        int s0 = g_srt_src[i], s1 = g_srt_src[i + 1];
        float v0 = g_srt_val[i], v1 = g_srt_val[i + 1];
        float4 a0 = ((const float4*)(h + (size_t)s0 * DIM_OUT))[c];
        float4 a1 = ((const float4*)(h + (size_t)s1 * DIM_OUT))[c];
        acc.x += a0.x * v0; acc.y += a0.y * v0;
        acc.z += a0.z * v0; acc.w += a0.w * v0;
        acc.x += a1.x * v1; acc.y += a1.y * v1;
        acc.z += a1.z * v1; acc.w += a1.w * v1;
    }
    if (i < end) {
        int s0 = g_srt_src[i];
        float v0 = g_srt_val[i];
        float4 a0 = ((const float4*)(h + (size_t)s0 * DIM_OUT))[c];
        acc.x += a0.x * v0; acc.y += a0.y * v0;
        acc.z += a0.z * v0; acc.w += a0.w * v0;
    }
    ((float4*)(out + (size_t)node * DIM_OUT))[c] = acc;
}

// u = tanh(h1) @ W23  (50000x64 @ 64x16), padded smem, f32x2
__global__ __launch_bounds__(256) void gemm2_tanh_kernel() {
    __shared__ float sh[64 * 65];
    __shared__ float4 sW[DIM_H * 4];
    int tid = threadIdx.x;
    int row0 = blockIdx.x * 64;

    const float4* W4 = (const float4*)g_W23;
    for (int i = tid; i < DIM_H * 4; i += 256) sW[i] = W4[i];
    for (int i = tid; i < 64 * 16; i += 256) {
        int r = i >> 4, k4 = i & 15;
        float4 a = (row0 + r < N_NODES)
            ? ((const float4*)(g_h1 + (size_t)(row0 + r) * DIM_H))[k4]
            : make_float4(0.f, 0.f, 0.f, 0.f);
        float* p = sh + r * 65 + 4 * k4;
        p[0] = tanh_fast(a.x); p[1] = tanh_fast(a.y);
        p[2] = tanh_fast(a.z); p[3] = tanh_fast(a.w);
    }
    __syncthreads();

    int r = tid >> 2;
    int c4 = tid & 3;
    unsigned long long acc0 = 0ull, acc1 = 0ull;
#pragma unroll 8
    for (int k = 0; k < DIM_H; k++) {
        float a = sh[r * 65 + k];
        unsigned long long aa = pack2(a, a);
        float4 w = sW[k * 4 + c4];
        fma2(acc0, aa, pack2(w.x, w.y));
        fma2(acc1, aa, pack2(w.z, w.w));
    }
    if (row0 + r < N_NODES) {
        float2 lo = unpack2(acc0), hi = unpack2(acc1);
        ((float4*)(g_u + (size_t)(row0 + r) * DIM_OUT))[c4] =
            make_float4(lo.x, lo.y, hi.x, hi.y);
    }
}

// softmax over dim 16
__global__ void softmax_kernel(float* __restrict__ out) {
    int r = blockIdx.x * blockDim.x + threadIdx.x;
    if (r >= N_NODES) return;
    const float4* p = (const float4*)(g_w + (size_t)r * DIM_OUT);
    float4 v0 = p[0], v1 = p[1], v2 = p[2], v3 = p[3];
    float vals[16] = {v0.x, v0.y, v0.z, v0.w, v1.x, v1.y, v1.z, v1.w,
                      v2.x, v2.y, v2.z, v2.w, v3.x, v3.y, v3.z, v3.w};
    float m = vals[0];
#pragma unroll
    for (int i = 1; i < 16; i++) m = fmaxf(m, vals[i]);
    float sum = 0.0f;
#pragma unroll
    for (int i = 0; i < 16; i++) {
        vals[i] = __expf(vals[i] - m);
        sum += vals[i];
    }
    float inv = __frcp_rn(sum);
    float4* q = (float4*)(out + (size_t)r * DIM_OUT);
    q[0] = make_float4(vals[0] * inv, vals[1] * inv, vals[2] * inv, vals[3] * inv);
    q[1] = make_float4(vals[4] * inv, vals[5] * inv, vals[6] * inv, vals[7] * inv);
    q[2] = make_float4(vals[8] * inv, vals[9] * inv, vals[10] * inv, vals[11] * inv);
    q[3] = make_float4(vals[12] * inv, vals[13] * inv, vals[14] * inv, vals[15] * inv);
}

extern "C" void kernel_launch(void* const* d_in, const int* in_sizes, int n_in,
                              void* d_out, int out_size) {
    const float* x         = (const float*)d_in[0];
    const int*   edge_src  = (const int*)d_in[1];
    const int*   edge_dst  = (const int*)d_in[2];
    const float* edge_vals = (const float*)d_in[3];
    const float* W1        = (const float*)d_in[4];
    const float* W2        = (const float*)d_in[5];
    const float* W3        = (const float*)d_in[6];
    float* out = (float*)d_out;

    float *h0, *h1, *u, *v, *w;
    int* hist;
    cudaGetSymbolAddress((void**)&h0, g_h0);
    cudaGetSymbolAddress((void**)&h1, g_h1);
    cudaGetSymbolAddress((void**)&u, g_u);
    cudaGetSymbolAddress((void**)&v, g_v);
    cudaGetSymbolAddress((void**)&w, g_w);
    cudaGetSymbolAddress((void**)&hist, g_hist);

    const int G1_SMEM = (DIM_IN * DIM_H + G1_ROWS * DIM_IN) * sizeof(float); // 64KB
    cudaFuncSetAttribute(gemm1_kernel,
                         cudaFuncAttributeMaxDynamicSharedMemorySize, G1_SMEM);

    // --- CSR build (counting sort by dst) ---
    cudaMemsetAsync(hist, 0, N_NODES * sizeof(int));
    hist_kernel<<<(N_EDGES / 4 + 255) / 256, 256>>>(edge_dst);
    scan1_kernel<<<SCAN_BLOCKS, 1024>>>();
    scan2_kernel<<<1, 32>>>();
    scan3_kernel<<<SCAN_BLOCKS, 1024>>>();
    scatter_kernel<<<(N_EDGES / 4 + 255) / 256, 256>>>(edge_src, edge_dst, edge_vals);

    // --- dense + SPMM pipeline ---
    w23_kernel<<<1, 1024>>>(W2, W3);
    gemm1_kernel<<<(N_NODES + G1_ROWS - 1) / G1_ROWS, 256, G1_SMEM>>>(x, W1);
    spmm64_csr_kernel<<<(N_NODES * 16 + 255) / 256, 256>>>(h0, h1);
    gemm2_tanh_kernel<<<(N_NODES + 63) / 64, 256>>>();
    spmm16_csr_kernel<<<(N_NODES * 4 + 255) / 256, 256>>>(u, v);
    spmm16_csr_kernel<<<(N_NODES * 4 + 255) / 256, 256>>>(v, w);
    softmax_kernel<<<(N_NODES + 255) / 256, 256>>>(out);
}